// round 10
// baseline (speedup 1.0000x reference)
#include <cuda_runtime.h>

// ----------------------------------------------------------------------------
// RNNDecoder: 3-layer GRU (H=128), T=256, B=1024, fc head (out=2).
//
// R9 = R8 (128 CTAs x 512 threads, 4-way K-split, f32x2, prefetched weights)
// + cross-cell software pipelining: the W_hh*h half-gemv of cell i+1 depends
// only on s_h[l'], written 2-3 cells earlier, so it is co-scheduled with
// combine(i). The previously serial combine tail (exchange LDS + MUFU chain)
// now overlaps ~384 FFMA2/thread of independent work, and the post-barrier
// FMA ramp starts warm. Still 2 barriers/cell.
//   cell: xGEMV(i) -> store partials -> B1 -> [combine(i) || hGEMV(i+1)] -> B2
// Biases live in smem (frees registers for the longer-lived acc_h).
// ----------------------------------------------------------------------------

namespace {
constexpr int LAYERS = 3;
constexpr int H      = 128;
constexpr int G3     = 3 * H;
constexpr int T      = 256;
constexpr int BC     = 8;
constexpr int NTHR   = 512;
constexpr int NBLK   = 128;        // 1024 / BC
constexpr int KKQ    = 8;          // float4 K-chunks per K-quarter

// dynamic smem layout (bytes)
constexpr int SMEM_X    = 0;       // float[1024]  s_x  [k][b]
constexpr int SMEM_H    = 4096;    // float[3072]  s_h  [l][k][b]
constexpr int SMEM_P    = 16384;   // ull[6144]    exchange [q][c][v][u]
constexpr int SMEM_FCW  = 65536;   // float[256]
constexpr int SMEM_FCB  = 66560;   // float[2]
constexpr int SMEM_BIAS = 66568;   // float[3*4*128] = [l][v][u]
constexpr int SMEM_TOTAL = 66568 + 6144;
}

typedef unsigned long long ull;

// Transposed weights, split per array: [l][kkp][g(r,z,n)][tid] float4,
// tid = grp*128 + u -> (unit u, K-quarter grp).
__device__ float4 g_wih[LAYERS * KKQ * 3 * NTHR];
__device__ float4 g_whh[LAYERS * KKQ * 3 * NTHR];

__global__ void prep_kernel(const float* __restrict__ wih,
                            const float* __restrict__ whh) {
  const int PER = LAYERS * KKQ * 3 * NTHR;
  int idx = blockIdx.x * blockDim.x + threadIdx.x;
  if (idx >= 2 * PER) return;
  int arr = idx / PER;
  int r   = idx % PER;
  int t   = r % NTHR;
  int g   = (r / NTHR) % 3;
  int kkp = (r / (NTHR * 3)) % KKQ;
  int l   = r / (NTHR * 3 * KKQ);
  int u   = t & 127, grp = t >> 7;
  int k4  = grp * KKQ + kkp;
  const float* src = (arr ? whh : wih) + (l * G3 + g * 128 + u) * H + k4 * 4;
  float4* dst = arr ? g_whh : g_wih;
  dst[((l * KKQ + kkp) * 3 + g) * NTHR + t] =
      *reinterpret_cast<const float4*>(src);
}

__device__ __forceinline__ void ffma2(ull& a, ull w, ull x) {
  asm("fma.rn.f32x2 %0, %1, %2, %0;" : "+l"(a) : "l"(w), "l"(x));
}
__device__ __forceinline__ void fadd2(ull& a, ull b) {
  asm("add.rn.f32x2 %0, %0, %1;" : "+l"(a) : "l"(b));
}
__device__ __forceinline__ ull dup2(float w) {
  ull r;
  asm("mov.b64 %0, {%1, %1};" : "=l"(r) : "f"(w));
  return r;
}
__device__ __forceinline__ float2 unpk(ull v) {
  float lo, hi;
  asm("mov.b64 {%0, %1}, %2;" : "=f"(lo), "=f"(hi) : "l"(v));
  return make_float2(lo, hi);
}
__device__ __forceinline__ ull pack2(float lo, float hi) {
  ull r;
  asm("mov.b64 %0, {%1, %2};" : "=l"(r) : "f"(lo), "f"(hi));
  return r;
}
__device__ __forceinline__ float sigm(float x) {
  return __fdividef(1.0f, 1.0f + __expf(-x));
}
__device__ __forceinline__ float tanh_fast(float v) {
  float a = fabsf(v);
  float e = __expf(-2.0f * a);
  float r = __fdividef(1.0f - e, 1.0f + e);
  return copysignf(r, v);
}
__device__ __forceinline__ float comp(const float4& v, int e) {
  return e == 0 ? v.x : e == 1 ? v.y : e == 2 ? v.z : v.w;
}

// One array's half-gemv over this thread's K-quarter: 3 gate rows x 8 batch.
// acc[g][q] lanes = batch-pair q. 24 LDG.128, 64 LDS.128, 384 FFMA2.
__device__ __forceinline__ void half_gemv(const float* __restrict__ act,
                                          const float4* __restrict__ wp,
                                          ull (&acc)[3][4]) {
#pragma unroll
  for (int g = 0; g < 3; g++)
#pragma unroll
    for (int q = 0; q < 4; q++) acc[g][q] = 0ull;

  float4 wv[3], wn[3];
#pragma unroll
  for (int i = 0; i < 3; i++) wn[i] = wp[i * NTHR];

#pragma unroll
  for (int kkp = 0; kkp < KKQ; kkp++) {
#pragma unroll
    for (int i = 0; i < 3; i++) wv[i] = wn[i];
    if (kkp < KKQ - 1) {
#pragma unroll
      for (int i = 0; i < 3; i++) wn[i] = wp[((kkp + 1) * 3 + i) * NTHR];
    }
#pragma unroll
    for (int e = 0; e < 4; e++) {
      int k8 = (kkp * 4 + e) * 8;
      ulonglong2 v0 = *reinterpret_cast<const ulonglong2*>(act + k8);
      ulonglong2 v1 = *reinterpret_cast<const ulonglong2*>(act + k8 + 4);
#pragma unroll
      for (int g = 0; g < 3; g++) {
        ull w2 = dup2(comp(wv[g], e));
        ffma2(acc[g][0], w2, v0.x);
        ffma2(acc[g][1], w2, v0.y);
        ffma2(acc[g][2], w2, v1.x);
        ffma2(acc[g][3], w2, v1.y);
      }
    }
  }
}

// Combine batch-pair Q: add 3 partner contributions, GRU gate math, write h.
template <int Q>
__device__ __forceinline__ void combine_pair(ull r2, ull z2, ull nx2, ull nh2,
                                             const ull* __restrict__ sp, int u,
                                             const float* __restrict__ sb,
                                             float* __restrict__ hl,
                                             float* __restrict__ sx) {
#pragma unroll
  for (int c = 0; c < 3; c++) {
    const ull* base = sp + (Q * 3 + c) * 4 * 128 + u;
    fadd2(r2,  base[0]);
    fadd2(z2,  base[128]);
    fadd2(nx2, base[256]);
    fadd2(nh2, base[384]);
  }
  float brz_r = sb[u], brz_z = sb[128 + u];
  float bn_x = sb[256 + u], bn_h = sb[384 + u];
  float2 rr = unpk(r2), zz = unpk(z2), xx = unpk(nx2), hh = unpk(nh2);
  float hp0 = hl[u * 8 + 2 * Q], hp1 = hl[u * 8 + 2 * Q + 1];
  float r0 = sigm(rr.x + brz_r), z0 = sigm(zz.x + brz_z);
  float n0 = tanh_fast(xx.x + bn_x + r0 * (hh.x + bn_h));
  float h0 = fmaf(z0, hp0 - n0, n0);
  float r1 = sigm(rr.y + brz_r), z1 = sigm(zz.y + brz_z);
  float n1 = tanh_fast(xx.y + bn_x + r1 * (hh.y + bn_h));
  float h1 = fmaf(z1, hp1 - n1, n1);
  ull o = pack2(h0, h1);
  *reinterpret_cast<ull*>(hl + u * 8 + 2 * Q) = o;
  *reinterpret_cast<ull*>(sx + u * 8 + 2 * Q) = o;
}

__global__ void __launch_bounds__(NTHR, 1)
gru_kernel(const float* __restrict__ hiddens,
           const float* __restrict__ b_ih,
           const float* __restrict__ b_hh,
           const float* __restrict__ fc_w,
           const float* __restrict__ fc_b,
           float* __restrict__ out) {
  extern __shared__ __align__(16) char dsm[];
  float* s_x    = reinterpret_cast<float*>(dsm + SMEM_X);
  float* s_h    = reinterpret_cast<float*>(dsm + SMEM_H);
  ull*   s_p    = reinterpret_cast<ull*>(dsm + SMEM_P);
  float* s_fcw  = reinterpret_cast<float*>(dsm + SMEM_FCW);
  float* s_fcb  = reinterpret_cast<float*>(dsm + SMEM_FCB);
  float* s_bias = reinterpret_cast<float*>(dsm + SMEM_BIAS);

  const int tid = threadIdx.x;
  const int u   = tid & 127;
  const int grp = tid >> 7;
  const int b0  = blockIdx.x * BC;

  // Biases -> smem: [l][v][u], v = {r(bi+bh), z(bi+bh), n_x(bi), n_h(bh)}.
  if (tid < 128) {
#pragma unroll
    for (int l = 0; l < LAYERS; l++) {
      s_bias[l * 512 + 0 * 128 + tid] =
          b_ih[l * G3 + tid] + b_hh[l * G3 + tid];
      s_bias[l * 512 + 1 * 128 + tid] =
          b_ih[l * G3 + 128 + tid] + b_hh[l * G3 + 128 + tid];
      s_bias[l * 512 + 2 * 128 + tid] = b_ih[l * G3 + 256 + tid];
      s_bias[l * 512 + 3 * 128 + tid] = b_hh[l * G3 + 256 + tid];
    }
  }
  if (tid < 256) s_fcw[tid] = fc_w[tid];
  if (tid < 2)   s_fcb[tid] = fc_b[tid];

  // h init: hiddens[b][l][k] -> s_h[l][k][b]
  for (int i = tid; i < LAYERS * H * BC; i += NTHR) {
    int l = i >> 10, rem = i & 1023, k = rem >> 3, b = rem & 7;
    s_h[i] = hiddens[(b0 + b) * (LAYERS * H) + l * H + k];
  }
  for (int i = tid; i < H * BC; i += NTHR) s_x[i] = 0.0f;
  __syncthreads();

  // Prologue: h half-gemv of cell 0 (layer 0).
  ull acch[3][4];
  half_gemv(s_h + grp * 256, g_whh + tid, acch);

  for (int t = 0; t < T; t++) {
#pragma unroll 1
    for (int l = 0; l < LAYERS; l++) {
      float* __restrict__ hl = s_h + l * (H * BC);

      // x half-gemv of the current cell (s_x stable since last barrier).
      ull accx[3][4];
      half_gemv(s_x + grp * 256, g_wih + l * (KKQ * 3 * NTHR) + tid, accx);

      // Merge r,z across arrays (only sums matter).
      ull rzr[4], rzz[4];
#pragma unroll
      for (int q = 0; q < 4; q++) {
        rzr[q] = accx[0][q]; fadd2(rzr[q], acch[0][q]);
        rzz[q] = accx[1][q]; fadd2(rzz[q], acch[1][q]);
      }

      // Store partials for the 3 batch-pairs this group does not own.
#pragma unroll
      for (int q = 0; q < 4; q++) {
        if (q == grp) continue;                    // runtime guard, const q
        int c = grp - (grp > q ? 1 : 0);
        ull* base = s_p + (q * 3 + c) * 4 * 128 + u;
        base[0]   = rzr[q];
        base[128] = rzz[q];
        base[256] = accx[2][q];
        base[384] = acch[2][q];
      }
      __syncthreads();                             // B1: partials visible

      // combine(i) interleaved with hGEMV(i+1): the next cell's W_hh gemv
      // reads s_h[ln], written 2-3 cells ago -> independent of combine.
      const float* sb = s_bias + l * 512;
      if (grp == 0)
        combine_pair<0>(rzr[0], rzz[0], accx[2][0], acch[2][0], s_p, u, sb,
                        hl, s_x);
      else if (grp == 1)
        combine_pair<1>(rzr[1], rzz[1], accx[2][1], acch[2][1], s_p, u, sb,
                        hl, s_x);
      else if (grp == 2)
        combine_pair<2>(rzr[2], rzz[2], accx[2][2], acch[2][2], s_p, u, sb,
                        hl, s_x);
      else
        combine_pair<3>(rzr[3], rzz[3], accx[2][3], acch[2][3], s_p, u, sb,
                        hl, s_x);

      int ln = (l == LAYERS - 1) ? 0 : l + 1;      // next cell's layer
      half_gemv(s_h + ln * (H * BC) + grp * 256,
                g_whh + ln * (KKQ * 3 * NTHR) + tid, acch);
      __syncthreads();                             // B2: s_x visible

      // fc head on top-layer output (reads s_x, stable until next combine).
      if (l == 2 && tid < 256) {
        int oid = tid >> 4, s = tid & 15;
        int o = oid & 1, b = oid >> 1;
        float p = 0.0f;
#pragma unroll
        for (int m = 0; m < 8; m++)
          p = fmaf(s_fcw[o * H + s * 8 + m], s_x[(s * 8 + m) * 8 + b], p);
        p += __shfl_down_sync(0xffffffffu, p, 8, 16);
        p += __shfl_down_sync(0xffffffffu, p, 4, 16);
        p += __shfl_down_sync(0xffffffffu, p, 2, 16);
        p += __shfl_down_sync(0xffffffffu, p, 1, 16);
        if (s == 0) out[((b0 + b) * T + t) * 2 + o] = p + s_fcb[o];
      }
    }
  }
}

extern "C" void kernel_launch(void* const* d_in, const int* in_sizes, int n_in,
                              void* d_out, int out_size) {
  (void)in_sizes; (void)n_in; (void)out_size;
  const float* hiddens = (const float*)d_in[0];
  const float* W_ih    = (const float*)d_in[1];
  const float* W_hh    = (const float*)d_in[2];
  const float* b_ih    = (const float*)d_in[3];
  const float* b_hh    = (const float*)d_in[4];
  const float* fc_w    = (const float*)d_in[5];
  const float* fc_b    = (const float*)d_in[6];
  float* out = (float*)d_out;

  cudaFuncSetAttribute(gru_kernel, cudaFuncAttributeMaxDynamicSharedMemorySize,
                       SMEM_TOTAL);

  const int prep_elems = 2 * LAYERS * KKQ * 3 * NTHR;
  prep_kernel<<<(prep_elems + 255) / 256, 256>>>(W_ih, W_hh);
  gru_kernel<<<NBLK, NTHR, SMEM_TOTAL>>>(hiddens, b_ih, b_hh, fc_w, fc_b, out);
}

// round 11
// speedup vs baseline: 1.0553x; 1.0553x over previous
#include <cuda_runtime.h>

// ----------------------------------------------------------------------------
// RNNDecoder: 3-layer GRU (H=128), T=256, B=1024, fc head (out=2).
//
// R9 = R8 (128 CTAs x 512 threads, 4-way K-split, f32x2, prefetched weights)
// + cross-cell software pipelining: the W_hh*h half-gemv of cell i+1 depends
// only on s_h[l'], written 2-3 cells earlier, so it is co-scheduled with
// combine(i). The previously serial combine tail (exchange LDS + MUFU chain)
// now overlaps ~384 FFMA2/thread of independent work, and the post-barrier
// FMA ramp starts warm. Still 2 barriers/cell.
//   cell: xGEMV(i) -> store partials -> B1 -> [combine(i) || hGEMV(i+1)] -> B2
// Biases live in smem (frees registers for the longer-lived acc_h).
// ----------------------------------------------------------------------------

namespace {
constexpr int LAYERS = 3;
constexpr int H      = 128;
constexpr int G3     = 3 * H;
constexpr int T      = 256;
constexpr int BC     = 8;
constexpr int NTHR   = 512;
constexpr int NBLK   = 128;        // 1024 / BC
constexpr int KKQ    = 8;          // float4 K-chunks per K-quarter

// dynamic smem layout (bytes)
constexpr int SMEM_X    = 0;       // float[1024]  s_x  [k][b]
constexpr int SMEM_H    = 4096;    // float[3072]  s_h  [l][k][b]
constexpr int SMEM_P    = 16384;   // ull[6144]    exchange [q][c][v][u]
constexpr int SMEM_FCW  = 65536;   // float[256]
constexpr int SMEM_FCB  = 66560;   // float[2]
constexpr int SMEM_BIAS = 66568;   // float[3*4*128] = [l][v][u]
constexpr int SMEM_TOTAL = 66568 + 6144;
}

typedef unsigned long long ull;

// Transposed weights, split per array: [l][kkp][g(r,z,n)][tid] float4,
// tid = grp*128 + u -> (unit u, K-quarter grp).
__device__ float4 g_wih[LAYERS * KKQ * 3 * NTHR];
__device__ float4 g_whh[LAYERS * KKQ * 3 * NTHR];

__global__ void prep_kernel(const float* __restrict__ wih,
                            const float* __restrict__ whh) {
  const int PER = LAYERS * KKQ * 3 * NTHR;
  int idx = blockIdx.x * blockDim.x + threadIdx.x;
  if (idx >= 2 * PER) return;
  int arr = idx / PER;
  int r   = idx % PER;
  int t   = r % NTHR;
  int g   = (r / NTHR) % 3;
  int kkp = (r / (NTHR * 3)) % KKQ;
  int l   = r / (NTHR * 3 * KKQ);
  int u   = t & 127, grp = t >> 7;
  int k4  = grp * KKQ + kkp;
  const float* src = (arr ? whh : wih) + (l * G3 + g * 128 + u) * H + k4 * 4;
  float4* dst = arr ? g_whh : g_wih;
  dst[((l * KKQ + kkp) * 3 + g) * NTHR + t] =
      *reinterpret_cast<const float4*>(src);
}

__device__ __forceinline__ void ffma2(ull& a, ull w, ull x) {
  asm("fma.rn.f32x2 %0, %1, %2, %0;" : "+l"(a) : "l"(w), "l"(x));
}
__device__ __forceinline__ void fadd2(ull& a, ull b) {
  asm("add.rn.f32x2 %0, %0, %1;" : "+l"(a) : "l"(b));
}
__device__ __forceinline__ ull dup2(float w) {
  ull r;
  asm("mov.b64 %0, {%1, %1};" : "=l"(r) : "f"(w));
  return r;
}
__device__ __forceinline__ float2 unpk(ull v) {
  float lo, hi;
  asm("mov.b64 {%0, %1}, %2;" : "=f"(lo), "=f"(hi) : "l"(v));
  return make_float2(lo, hi);
}
__device__ __forceinline__ ull pack2(float lo, float hi) {
  ull r;
  asm("mov.b64 %0, {%1, %2};" : "=l"(r) : "f"(lo), "f"(hi));
  return r;
}
__device__ __forceinline__ float sigm(float x) {
  return __fdividef(1.0f, 1.0f + __expf(-x));
}
__device__ __forceinline__ float tanh_fast(float v) {
  float a = fabsf(v);
  float e = __expf(-2.0f * a);
  float r = __fdividef(1.0f - e, 1.0f + e);
  return copysignf(r, v);
}
__device__ __forceinline__ float comp(const float4& v, int e) {
  return e == 0 ? v.x : e == 1 ? v.y : e == 2 ? v.z : v.w;
}

// One array's half-gemv over this thread's K-quarter: 3 gate rows x 8 batch.
// acc[g][q] lanes = batch-pair q. 24 LDG.128, 64 LDS.128, 384 FFMA2.
__device__ __forceinline__ void half_gemv(const float* __restrict__ act,
                                          const float4* __restrict__ wp,
                                          ull (&acc)[3][4]) {
#pragma unroll
  for (int g = 0; g < 3; g++)
#pragma unroll
    for (int q = 0; q < 4; q++) acc[g][q] = 0ull;

  float4 wv[3], wn[3];
#pragma unroll
  for (int i = 0; i < 3; i++) wn[i] = wp[i * NTHR];

#pragma unroll
  for (int kkp = 0; kkp < KKQ; kkp++) {
#pragma unroll
    for (int i = 0; i < 3; i++) wv[i] = wn[i];
    if (kkp < KKQ - 1) {
#pragma unroll
      for (int i = 0; i < 3; i++) wn[i] = wp[((kkp + 1) * 3 + i) * NTHR];
    }
#pragma unroll
    for (int e = 0; e < 4; e++) {
      int k8 = (kkp * 4 + e) * 8;
      ulonglong2 v0 = *reinterpret_cast<const ulonglong2*>(act + k8);
      ulonglong2 v1 = *reinterpret_cast<const ulonglong2*>(act + k8 + 4);
#pragma unroll
      for (int g = 0; g < 3; g++) {
        ull w2 = dup2(comp(wv[g], e));
        ffma2(acc[g][0], w2, v0.x);
        ffma2(acc[g][1], w2, v0.y);
        ffma2(acc[g][2], w2, v1.x);
        ffma2(acc[g][3], w2, v1.y);
      }
    }
  }
}

// Combine batch-pair Q: add 3 partner contributions, GRU gate math, write h.
template <int Q>
__device__ __forceinline__ void combine_pair(ull r2, ull z2, ull nx2, ull nh2,
                                             const ull* __restrict__ sp, int u,
                                             const float* __restrict__ sb,
                                             float* __restrict__ hl,
                                             float* __restrict__ sx) {
#pragma unroll
  for (int c = 0; c < 3; c++) {
    const ull* base = sp + (Q * 3 + c) * 4 * 128 + u;
    fadd2(r2,  base[0]);
    fadd2(z2,  base[128]);
    fadd2(nx2, base[256]);
    fadd2(nh2, base[384]);
  }
  float brz_r = sb[u], brz_z = sb[128 + u];
  float bn_x = sb[256 + u], bn_h = sb[384 + u];
  float2 rr = unpk(r2), zz = unpk(z2), xx = unpk(nx2), hh = unpk(nh2);
  float hp0 = hl[u * 8 + 2 * Q], hp1 = hl[u * 8 + 2 * Q + 1];
  float r0 = sigm(rr.x + brz_r), z0 = sigm(zz.x + brz_z);
  float n0 = tanh_fast(xx.x + bn_x + r0 * (hh.x + bn_h));
  float h0 = fmaf(z0, hp0 - n0, n0);
  float r1 = sigm(rr.y + brz_r), z1 = sigm(zz.y + brz_z);
  float n1 = tanh_fast(xx.y + bn_x + r1 * (hh.y + bn_h));
  float h1 = fmaf(z1, hp1 - n1, n1);
  ull o = pack2(h0, h1);
  *reinterpret_cast<ull*>(hl + u * 8 + 2 * Q) = o;
  *reinterpret_cast<ull*>(sx + u * 8 + 2 * Q) = o;
}

__global__ void __launch_bounds__(NTHR, 1)
gru_kernel(const float* __restrict__ hiddens,
           const float* __restrict__ b_ih,
           const float* __restrict__ b_hh,
           const float* __restrict__ fc_w,
           const float* __restrict__ fc_b,
           float* __restrict__ out) {
  extern __shared__ __align__(16) char dsm[];
  float* s_x    = reinterpret_cast<float*>(dsm + SMEM_X);
  float* s_h    = reinterpret_cast<float*>(dsm + SMEM_H);
  ull*   s_p    = reinterpret_cast<ull*>(dsm + SMEM_P);
  float* s_fcw  = reinterpret_cast<float*>(dsm + SMEM_FCW);
  float* s_fcb  = reinterpret_cast<float*>(dsm + SMEM_FCB);
  float* s_bias = reinterpret_cast<float*>(dsm + SMEM_BIAS);

  const int tid = threadIdx.x;
  const int u   = tid & 127;
  const int grp = tid >> 7;
  const int b0  = blockIdx.x * BC;

  // Biases -> smem: [l][v][u], v = {r(bi+bh), z(bi+bh), n_x(bi), n_h(bh)}.
  if (tid < 128) {
#pragma unroll
    for (int l = 0; l < LAYERS; l++) {
      s_bias[l * 512 + 0 * 128 + tid] =
          b_ih[l * G3 + tid] + b_hh[l * G3 + tid];
      s_bias[l * 512 + 1 * 128 + tid] =
          b_ih[l * G3 + 128 + tid] + b_hh[l * G3 + 128 + tid];
      s_bias[l * 512 + 2 * 128 + tid] = b_ih[l * G3 + 256 + tid];
      s_bias[l * 512 + 3 * 128 + tid] = b_hh[l * G3 + 256 + tid];
    }
  }
  if (tid < 256) s_fcw[tid] = fc_w[tid];
  if (tid < 2)   s_fcb[tid] = fc_b[tid];

  // h init: hiddens[b][l][k] -> s_h[l][k][b]
  for (int i = tid; i < LAYERS * H * BC; i += NTHR) {
    int l = i >> 10, rem = i & 1023, k = rem >> 3, b = rem & 7;
    s_h[i] = hiddens[(b0 + b) * (LAYERS * H) + l * H + k];
  }
  for (int i = tid; i < H * BC; i += NTHR) s_x[i] = 0.0f;
  __syncthreads();

  // Prologue: h half-gemv of cell 0 (layer 0).
  ull acch[3][4];
  half_gemv(s_h + grp * 256, g_whh + tid, acch);

  for (int t = 0; t < T; t++) {
#pragma unroll 1
    for (int l = 0; l < LAYERS; l++) {
      float* __restrict__ hl = s_h + l * (H * BC);

      // x half-gemv of the current cell (s_x stable since last barrier).
      ull accx[3][4];
      half_gemv(s_x + grp * 256, g_wih + l * (KKQ * 3 * NTHR) + tid, accx);

      // Merge r,z across arrays (only sums matter).
      ull rzr[4], rzz[4];
#pragma unroll
      for (int q = 0; q < 4; q++) {
        rzr[q] = accx[0][q]; fadd2(rzr[q], acch[0][q]);
        rzz[q] = accx[1][q]; fadd2(rzz[q], acch[1][q]);
      }

      // Store partials for the 3 batch-pairs this group does not own.
#pragma unroll
      for (int q = 0; q < 4; q++) {
        if (q == grp) continue;                    // runtime guard, const q
        int c = grp - (grp > q ? 1 : 0);
        ull* base = s_p + (q * 3 + c) * 4 * 128 + u;
        base[0]   = rzr[q];
        base[128] = rzz[q];
        base[256] = accx[2][q];
        base[384] = acch[2][q];
      }
      __syncthreads();                             // B1: partials visible

      // combine(i) interleaved with hGEMV(i+1): the next cell's W_hh gemv
      // reads s_h[ln], written 2-3 cells ago -> independent of combine.
      const float* sb = s_bias + l * 512;
      if (grp == 0)
        combine_pair<0>(rzr[0], rzz[0], accx[2][0], acch[2][0], s_p, u, sb,
                        hl, s_x);
      else if (grp == 1)
        combine_pair<1>(rzr[1], rzz[1], accx[2][1], acch[2][1], s_p, u, sb,
                        hl, s_x);
      else if (grp == 2)
        combine_pair<2>(rzr[2], rzz[2], accx[2][2], acch[2][2], s_p, u, sb,
                        hl, s_x);
      else
        combine_pair<3>(rzr[3], rzz[3], accx[2][3], acch[2][3], s_p, u, sb,
                        hl, s_x);

      int ln = (l == LAYERS - 1) ? 0 : l + 1;      // next cell's layer
      half_gemv(s_h + ln * (H * BC) + grp * 256,
                g_whh + ln * (KKQ * 3 * NTHR) + tid, acch);
      __syncthreads();                             // B2: s_x visible

      // fc head on top-layer output (reads s_x, stable until next combine).
      if (l == 2 && tid < 256) {
        int oid = tid >> 4, s = tid & 15;
        int o = oid & 1, b = oid >> 1;
        float p = 0.0f;
#pragma unroll
        for (int m = 0; m < 8; m++)
          p = fmaf(s_fcw[o * H + s * 8 + m], s_x[(s * 8 + m) * 8 + b], p);
        p += __shfl_down_sync(0xffffffffu, p, 8, 16);
        p += __shfl_down_sync(0xffffffffu, p, 4, 16);
        p += __shfl_down_sync(0xffffffffu, p, 2, 16);
        p += __shfl_down_sync(0xffffffffu, p, 1, 16);
        if (s == 0) out[((b0 + b) * T + t) * 2 + o] = p + s_fcb[o];
      }
    }
  }
}

extern "C" void kernel_launch(void* const* d_in, const int* in_sizes, int n_in,
                              void* d_out, int out_size) {
  (void)in_sizes; (void)n_in; (void)out_size;
  const float* hiddens = (const float*)d_in[0];
  const float* W_ih    = (const float*)d_in[1];
  const float* W_hh    = (const float*)d_in[2];
  const float* b_ih    = (const float*)d_in[3];
  const float* b_hh    = (const float*)d_in[4];
  const float* fc_w    = (const float*)d_in[5];
  const float* fc_b    = (const float*)d_in[6];
  float* out = (float*)d_out;

  cudaFuncSetAttribute(gru_kernel, cudaFuncAttributeMaxDynamicSharedMemorySize,
                       SMEM_TOTAL);

  const int prep_elems = 2 * LAYERS * KKQ * 3 * NTHR;
  prep_kernel<<<(prep_elems + 255) / 256, 256>>>(W_ih, W_hh);
  gru_kernel<<<NBLK, NTHR, SMEM_TOTAL>>>(hiddens, b_ih, b_hh, fc_w, fc_b, out);
}